// round 10
// baseline (speedup 1.0000x reference)
#include <cuda_runtime.h>
#include <cuda_fp16.h>
#include <cstdint>

#define N_NODES 100000
#define N_EDGES 1600000
#define NBLK 391          // ceil(N_NODES/256)
#define FULLM 0xFFFFFFFFu

// ---------------- device scratch ----------------
__device__ __half g_hh[(size_t)N_NODES * 64];   // fp16 gather operand
__device__ float  g_y[(size_t)N_NODES * 64];
__device__ float  g_a[(size_t)N_NODES * 32];
__device__ int    g_cnt[N_NODES + 512];         // counts + lookback state tail
__device__ float  g_dinv[N_NODES];
__device__ int    g_offs[N_NODES + 1];
__device__ int    g_rank[N_EDGES];              // packed (dst<<14)|rank
__device__ int    g_srcl[N_EDGES];              // CSR src indices
__device__ int    g_is64;

// ---------------- helpers ----------------
__device__ __forceinline__ int clampn(long long v) {
    if (v < 0) v = 0;
    if (v >= N_NODES) v = N_NODES - 1;
    return (int)v;
}

__global__ void detect_k(const int* __restrict__ ei32) {
    int lane = threadIdx.x;
    int nz = (ei32[2 * lane + 1] != 0);
    unsigned m = __ballot_sync(FULLM, nz);
    if (lane == 0) g_is64 = (m == 0) ? 1 : 0;
}

// count in-degree, pack (dst<<14)|rank per edge; 4 edges/thread
__global__ void count_k(const void* __restrict__ ei) {
    int e0 = (blockIdx.x * blockDim.x + threadIdx.x) * 4;
    if (e0 >= N_EDGES) return;
    int d0, d1, d2, d3;
    if (!g_is64) {
        int4 v = *reinterpret_cast<const int4*>((const int*)ei + N_EDGES + e0);
        d0 = clampn(v.x); d1 = clampn(v.y); d2 = clampn(v.z); d3 = clampn(v.w);
    } else {
        const long long* p = (const long long*)ei + N_EDGES + e0;
        d0 = clampn(p[0]); d1 = clampn(p[1]); d2 = clampn(p[2]); d3 = clampn(p[3]);
    }
    int4 r;
    r.x = (d0 << 14) | atomicAdd(&g_cnt[d0], 1);
    r.y = (d1 << 14) | atomicAdd(&g_cnt[d1], 1);
    r.z = (d2 << 14) | atomicAdd(&g_cnt[d2], 1);
    r.w = (d3 << 14) | atomicAdd(&g_cnt[d3], 1);
    *reinterpret_cast<int4*>(g_rank + e0) = r;
}

// single-pass exclusive scan (decoupled lookback) + fused dinv
__global__ void scan_k() {
    __shared__ int wsum[8];
    __shared__ int s_base;
    unsigned* state = (unsigned*)(g_cnt + N_NODES);
    int tid = threadIdx.x, b = blockIdx.x;
    int i = b * 256 + tid;
    int c = (i < N_NODES) ? g_cnt[i] : 0;
    if (i < N_NODES) g_dinv[i] = rsqrtf((float)c + 1.0f);
    int lane = tid & 31, wid = tid >> 5;

    int inc = c;                                  // warp inclusive scan
#pragma unroll
    for (int d = 1; d < 32; d <<= 1) {
        int t = __shfl_up_sync(FULLM, inc, d);
        if (lane >= d) inc += t;
    }
    if (lane == 31) wsum[wid] = inc;
    __syncthreads();
    if (wid == 0) {
        int v = (lane < 8) ? wsum[lane] : 0;
#pragma unroll
        for (int d = 1; d < 8; d <<= 1) {
            int t = __shfl_up_sync(FULLM, v, d);
            if (lane >= d) v += t;
        }
        if (lane < 8) wsum[lane] = v;
    }
    __syncthreads();
    int warpbase = (wid == 0) ? 0 : wsum[wid - 1];
    int lex = warpbase + inc - c;                 // block-local exclusive
    int btot = wsum[7];

    if (tid == 0) {
        if (b == 0) {
            __threadfence();
            atomicExch(&state[0], (2u << 30) | (unsigned)btot);
            s_base = 0;
        } else {
            __threadfence();
            atomicExch(&state[b], (1u << 30) | (unsigned)btot);
            int running = 0;
            int p = b - 1;
            while (true) {
                unsigned st = atomicAdd(&state[p], 0u);
                unsigned status = st >> 30;
                if (status == 0u) { __nanosleep(40); continue; }
                running += (int)(st & 0x3FFFFFFFu);
                if (status == 2u) break;
                p--;
            }
            __threadfence();
            atomicExch(&state[b], (2u << 30) | (unsigned)(running + btot));
            s_base = running;
        }
    }
    __syncthreads();
    int base = s_base;
    if (i < N_NODES) g_offs[i] = base + lex;
    if (i == N_NODES - 1) g_offs[N_NODES] = base + lex + c;
}

// scatter src into CSR slots — no atomics, dst+rank from packed word; 4 edges/thread
__global__ void fill_k(const void* __restrict__ ei) {
    int e0 = (blockIdx.x * blockDim.x + threadIdx.x) * 4;
    if (e0 >= N_EDGES) return;
    int s0, s1, s2, s3;
    if (!g_is64) {
        int4 v = *reinterpret_cast<const int4*>((const int*)ei + e0);
        s0 = clampn(v.x); s1 = clampn(v.y); s2 = clampn(v.z); s3 = clampn(v.w);
    } else {
        const long long* p = (const long long*)ei + e0;
        s0 = clampn(p[0]); s1 = clampn(p[1]); s2 = clampn(p[2]); s3 = clampn(p[3]);
    }
    int4 pr = *reinterpret_cast<const int4*>(g_rank + e0);
    g_srcl[g_offs[pr.x >> 14] + (pr.x & 0x3FFF)] = s0;
    g_srcl[g_offs[pr.y >> 14] + (pr.y & 0x3FFF)] = s1;
    g_srcl[g_offs[pr.z >> 14] + (pr.z & 0x3FFF)] = s2;
    g_srcl[g_offs[pr.w >> 14] + (pr.w & 0x3FFF)] = s3;
}

// x' = half(dinv[i] * x), 4 features per thread
__global__ void scale_k(const float* __restrict__ x, __half* __restrict__ xs) {
    int i = blockIdx.x * blockDim.x + threadIdx.x;
    if (i < N_NODES * 8) {
        int node = i >> 3;
        float dv = g_dinv[node];
        float4 v = reinterpret_cast<const float4*>(x)[i];
        __half2 h0 = __floats2half2_rn(v.x * dv, v.y * dv);
        __half2 h1 = __floats2half2_rn(v.z * dv, v.w * dv);
        uint2 u;
        u.x = *reinterpret_cast<uint32_t*>(&h0);
        u.y = *reinterpret_cast<uint32_t*>(&h1);
        reinterpret_cast<uint2*>(xs)[i] = u;
    }
}

// ---------------- GEMM: out[N,FOUT] = in[N,FIN] @ W^T
template<int FIN, int FOUT, bool BR, bool OUTH>
__global__ void gemm_k(const float* __restrict__ x, const float* __restrict__ W,
                       const float* __restrict__ bias, void* __restrict__ hout) {
    constexpr int TPR = FOUT / 4;
    constexpr int RPB = 256 / TPR;
    __shared__ float Ws[FIN * FOUT];
    for (int i = threadIdx.x; i < FIN * FOUT; i += 256) {
        int f = i / FIN, k = i % FIN;
        Ws[k * FOUT + f] = W[i];
    }
    __syncthreads();

    int r  = threadIdx.x / TPR;
    int c0 = (threadIdx.x % TPR) * 4;
    int row = blockIdx.x * RPB + r;
    if (row >= N_NODES) return;

    const float4* __restrict__ xr = reinterpret_cast<const float4*>(x + (size_t)row * FIN);
    float a0 = 0.f, a1 = 0.f, a2 = 0.f, a3 = 0.f;
#pragma unroll
    for (int k4 = 0; k4 < FIN / 4; k4++) {
        float4 xv = xr[k4];
        const float4 w0 = *reinterpret_cast<const float4*>(&Ws[(4 * k4 + 0) * FOUT + c0]);
        const float4 w1 = *reinterpret_cast<const float4*>(&Ws[(4 * k4 + 1) * FOUT + c0]);
        const float4 w2 = *reinterpret_cast<const float4*>(&Ws[(4 * k4 + 2) * FOUT + c0]);
        const float4 w3 = *reinterpret_cast<const float4*>(&Ws[(4 * k4 + 3) * FOUT + c0]);
        a0 = fmaf(xv.x, w0.x, a0); a1 = fmaf(xv.x, w0.y, a1);
        a2 = fmaf(xv.x, w0.z, a2); a3 = fmaf(xv.x, w0.w, a3);
        a0 = fmaf(xv.y, w1.x, a0); a1 = fmaf(xv.y, w1.y, a1);
        a2 = fmaf(xv.y, w1.z, a2); a3 = fmaf(xv.y, w1.w, a3);
        a0 = fmaf(xv.z, w2.x, a0); a1 = fmaf(xv.z, w2.y, a1);
        a2 = fmaf(xv.z, w2.z, a2); a3 = fmaf(xv.z, w2.w, a3);
        a0 = fmaf(xv.w, w3.x, a0); a1 = fmaf(xv.w, w3.y, a1);
        a2 = fmaf(xv.w, w3.z, a2); a3 = fmaf(xv.w, w3.w, a3);
    }
    if (BR) {
        a0 = fmaxf(a0 + bias[c0 + 0], 0.f);
        a1 = fmaxf(a1 + bias[c0 + 1], 0.f);
        a2 = fmaxf(a2 + bias[c0 + 2], 0.f);
        a3 = fmaxf(a3 + bias[c0 + 3], 0.f);
    }
    if (OUTH) {
        float dv = g_dinv[row];
        __half2 h0 = __floats2half2_rn(a0 * dv, a1 * dv);
        __half2 h1 = __floats2half2_rn(a2 * dv, a3 * dv);
        uint2 u;
        u.x = *reinterpret_cast<uint32_t*>(&h0);
        u.y = *reinterpret_cast<uint32_t*>(&h1);
        reinterpret_cast<uint2*>(hout)[((size_t)row * FOUT + c0) >> 2] = u;
    } else {
        reinterpret_cast<float4*>(hout)[((size_t)row * FOUT + c0) >> 2] =
            make_float4(a0, a1, a2, a3);
    }
}

__device__ __forceinline__ void acc_half4(float& ax, float& ay, float& az, float& aw,
                                          uint2 u) {
    __half2 p0 = *reinterpret_cast<__half2*>(&u.x);
    __half2 p1 = *reinterpret_cast<__half2*>(&u.y);
    float2 f0 = __half22float2(p0);
    float2 f1 = __half22float2(p1);
    ax += f0.x; ay += f0.y; az += f1.x; aw += f1.y;
}

// ---------------- agg F=64 (fp16 in): 16 lanes x 4 halves per edge, 2 edges/iter
template<bool BR>
__global__ void agg64_k(const __half* __restrict__ h, const float* __restrict__ bias,
                        float* __restrict__ out) {
    int node = (blockIdx.x * blockDim.x + threadIdx.x) >> 5;
    int lane = threadIdx.x & 31;
    if (node >= N_NODES) return;
    int half = lane >> 4;
    int fl   = lane & 15;
    const uint2* __restrict__ h8 = reinterpret_cast<const uint2*>(h);

    int beg = g_offs[node];
    int end = g_offs[node + 1];

    float ax = 0.f, ay = 0.f, az = 0.f, aw = 0.f;
    int j = beg + half;
    for (; j + 2 < end; j += 4) {
        int s0 = g_srcl[j];
        int s1 = g_srcl[j + 2];
        uint2 u0 = h8[(size_t)s0 * 16 + fl];
        uint2 u1 = h8[(size_t)s1 * 16 + fl];
        acc_half4(ax, ay, az, aw, u0);
        acc_half4(ax, ay, az, aw, u1);
    }
    if (j < end) {
        int s = g_srcl[j];
        acc_half4(ax, ay, az, aw, h8[(size_t)s * 16 + fl]);
    }

    ax += __shfl_xor_sync(FULLM, ax, 16);
    ay += __shfl_xor_sync(FULLM, ay, 16);
    az += __shfl_xor_sync(FULLM, az, 16);
    aw += __shfl_xor_sync(FULLM, aw, 16);

    if (half == 0) {
        float dv = g_dinv[node];
        acc_half4(ax, ay, az, aw, h8[(size_t)node * 16 + fl]);   // self loop
        ax *= dv; ay *= dv; az *= dv; aw *= dv;
        if (BR) {
            const float4 bv = reinterpret_cast<const float4*>(bias)[fl];
            ax = fmaxf(ax + bv.x, 0.f); ay = fmaxf(ay + bv.y, 0.f);
            az = fmaxf(az + bv.z, 0.f); aw = fmaxf(aw + bv.w, 0.f);
        }
        reinterpret_cast<float4*>(out)[(size_t)node * 16 + fl] =
            make_float4(ax, ay, az, aw);
    }
}

// ---------------- agg F=32 (fp16 in): 8 lanes x 4 halves per edge, 4 edges/iter
template<bool BR>
__global__ void agg32_k(const __half* __restrict__ h, const float* __restrict__ bias,
                        float* __restrict__ out) {
    int node = (blockIdx.x * blockDim.x + threadIdx.x) >> 5;
    int lane = threadIdx.x & 31;
    if (node >= N_NODES) return;
    int q  = lane >> 3;
    int fl = lane & 7;
    const uint2* __restrict__ h8 = reinterpret_cast<const uint2*>(h);

    int beg = g_offs[node];
    int end = g_offs[node + 1];

    float ax = 0.f, ay = 0.f, az = 0.f, aw = 0.f;
    int j = beg + q;
    for (; j + 4 < end; j += 8) {
        int s0 = g_srcl[j];
        int s1 = g_srcl[j + 4];
        uint2 u0 = h8[(size_t)s0 * 8 + fl];
        uint2 u1 = h8[(size_t)s1 * 8 + fl];
        acc_half4(ax, ay, az, aw, u0);
        acc_half4(ax, ay, az, aw, u1);
    }
    if (j < end) {
        int s = g_srcl[j];
        acc_half4(ax, ay, az, aw, h8[(size_t)s * 8 + fl]);
    }

    ax += __shfl_xor_sync(FULLM, ax, 8);
    ay += __shfl_xor_sync(FULLM, ay, 8);
    az += __shfl_xor_sync(FULLM, az, 8);
    aw += __shfl_xor_sync(FULLM, aw, 8);
    ax += __shfl_xor_sync(FULLM, ax, 16);
    ay += __shfl_xor_sync(FULLM, ay, 16);
    az += __shfl_xor_sync(FULLM, az, 16);
    aw += __shfl_xor_sync(FULLM, aw, 16);

    if (q == 0) {
        float dv = g_dinv[node];
        acc_half4(ax, ay, az, aw, h8[(size_t)node * 8 + fl]);    // self loop
        ax *= dv; ay *= dv; az *= dv; aw *= dv;
        if (BR) {
            const float4 bv = reinterpret_cast<const float4*>(bias)[fl];
            ax = fmaxf(ax + bv.x, 0.f); ay = fmaxf(ay + bv.y, 0.f);
            az = fmaxf(az + bv.z, 0.f); aw = fmaxf(aw + bv.w, 0.f);
        }
        reinterpret_cast<float4*>(out)[(size_t)node * 8 + fl] =
            make_float4(ax, ay, az, aw);
    }
}

// ---------------- launch ----------------
extern "C" void kernel_launch(void* const* d_in, const int* in_sizes, int n_in,
                              void* d_out, int out_size) {
    const float* x  = (const float*)d_in[0];
    const void*  ei = d_in[1];
    const float* W1 = (const float*)d_in[2];
    const float* b1 = (const float*)d_in[3];
    const float* W2 = (const float*)d_in[4];
    const float* b2 = (const float*)d_in[5];
    const float* W3 = (const float*)d_in[6];
    const float* b3 = (const float*)d_in[7];
    float* out = (float*)d_out;

    void *phh, *py, *pa, *pc;
    cudaGetSymbolAddress(&phh, g_hh);
    cudaGetSymbolAddress(&py, g_y);
    cudaGetSymbolAddress(&pa, g_a);
    cudaGetSymbolAddress(&pc, g_cnt);
    __half* hh = (__half*)phh;
    float*  y  = (float*)py;
    float*  a  = (float*)pa;

    const int TB = 256;
    const int WGRID = (N_NODES * 32 + TB - 1) / TB;
    const int EGRID4 = (N_EDGES / 4 + TB - 1) / TB;

    // dtype detect + CSR build
    detect_k<<<1, 32>>>((const int*)ei);
    cudaMemsetAsync(pc, 0, (N_NODES + 512) * sizeof(int));   // counts + lookback state
    count_k<<<EGRID4, TB>>>(ei);
    scan_k <<<NBLK, TB>>>();                                  // dinv + offs, single pass
    fill_k <<<EGRID4, TB>>>(ei);

    // Layer 1
    scale_k<<<(N_NODES * 8 + TB - 1) / TB, TB>>>(x, hh);
    agg32_k<false><<<WGRID, TB>>>(hh, nullptr, a);
    gemm_k<32, 64, true, false><<<N_NODES / 16, TB>>>(a, W1, b1, y);
    // Layer 2
    gemm_k<64, 64, false, true><<<N_NODES / 16, TB>>>(y, W2, nullptr, hh);
    agg64_k<true><<<WGRID, TB>>>(hh, b2, y);
    // Layer 3
    gemm_k<64, 32, false, true><<<N_NODES / 32, TB>>>(y, W3, nullptr, hh);
    agg32_k<true><<<WGRID, TB>>>(hh, b3, out);

    (void)in_sizes; (void)n_in; (void)out_size;
}

// round 12
// speedup vs baseline: 1.0046x; 1.0046x over previous
#include <cuda_runtime.h>
#include <cuda_fp16.h>
#include <cstdint>

#define N_NODES 100000
#define N_EDGES 1600000
#define NBLK 391          // ceil(N_NODES/256)
#define FULLM 0xFFFFFFFFu

// ---------------- device scratch ----------------
__device__ __half g_hh[(size_t)N_NODES * 64];   // fp16 gather operand
__device__ float  g_y[(size_t)N_NODES * 64];
__device__ float  g_a[(size_t)N_NODES * 32];
__device__ int    g_cnt[N_NODES + 512];         // counts + lookback state tail
__device__ float  g_dinv[N_NODES];
__device__ int    g_offs[N_NODES + 1];
__device__ int    g_rank[N_EDGES];              // packed (dst<<14)|rank
__device__ int    g_srcl[N_EDGES];              // CSR src indices
__device__ int    g_is64;

// ---------------- helpers ----------------
__device__ __forceinline__ int clampn(long long v) {
    if (v < 0) v = 0;
    if (v >= N_NODES) v = N_NODES - 1;
    return (int)v;
}

// zero counts + lookback state; block 0 warp 0 detects dtype
__global__ void init_detect_k(const int* __restrict__ ei32) {
    int i = blockIdx.x * blockDim.x + threadIdx.x;
    if (i < N_NODES + 512) g_cnt[i] = 0;
    if (blockIdx.x == 0 && threadIdx.x < 32) {
        int lane = threadIdx.x;
        int nz = (ei32[2 * lane + 1] != 0);
        unsigned m = __ballot_sync(FULLM, nz);
        if (lane == 0) g_is64 = (m == 0) ? 1 : 0;
    }
}

// count in-degree, pack (dst<<14)|rank per edge; 4 edges/thread
__global__ void count_k(const void* __restrict__ ei) {
    int e0 = (blockIdx.x * blockDim.x + threadIdx.x) * 4;
    if (e0 >= N_EDGES) return;
    int d0, d1, d2, d3;
    if (!g_is64) {
        int4 v = *reinterpret_cast<const int4*>((const int*)ei + N_EDGES + e0);
        d0 = clampn(v.x); d1 = clampn(v.y); d2 = clampn(v.z); d3 = clampn(v.w);
    } else {
        const long long* p = (const long long*)ei + N_EDGES + e0;
        d0 = clampn(p[0]); d1 = clampn(p[1]); d2 = clampn(p[2]); d3 = clampn(p[3]);
    }
    int4 r;
    r.x = (d0 << 14) | atomicAdd(&g_cnt[d0], 1);
    r.y = (d1 << 14) | atomicAdd(&g_cnt[d1], 1);
    r.z = (d2 << 14) | atomicAdd(&g_cnt[d2], 1);
    r.w = (d3 << 14) | atomicAdd(&g_cnt[d3], 1);
    *reinterpret_cast<int4*>(g_rank + e0) = r;
}

// single-pass exclusive scan (decoupled lookback) + fused dinv + fused x prescale
__global__ void scan_k(const float* __restrict__ x) {
    __shared__ int wsum[8];
    __shared__ int s_base;
    unsigned* state = (unsigned*)(g_cnt + N_NODES);
    int tid = threadIdx.x, b = blockIdx.x;
    int i = b * 256 + tid;
    int c = (i < N_NODES) ? g_cnt[i] : 0;
    float dv = rsqrtf((float)c + 1.0f);
    if (i < N_NODES) g_dinv[i] = dv;
    int lane = tid & 31, wid = tid >> 5;

    int inc = c;                                  // warp inclusive scan
#pragma unroll
    for (int d = 1; d < 32; d <<= 1) {
        int t = __shfl_up_sync(FULLM, inc, d);
        if (lane >= d) inc += t;
    }
    if (lane == 31) wsum[wid] = inc;
    __syncthreads();
    if (wid == 0) {
        int v = (lane < 8) ? wsum[lane] : 0;
#pragma unroll
        for (int d = 1; d < 8; d <<= 1) {
            int t = __shfl_up_sync(FULLM, v, d);
            if (lane >= d) v += t;
        }
        if (lane < 8) wsum[lane] = v;
    }
    __syncthreads();
    int warpbase = (wid == 0) ? 0 : wsum[wid - 1];
    int lex = warpbase + inc - c;                 // block-local exclusive
    int btot = wsum[7];

    if (tid == 0) {
        if (b == 0) {
            __threadfence();
            atomicExch(&state[0], (2u << 30) | (unsigned)btot);
            s_base = 0;
        } else {
            __threadfence();
            atomicExch(&state[b], (1u << 30) | (unsigned)btot);
            int running = 0;
            int p = b - 1;
            while (true) {
                unsigned st = atomicAdd(&state[p], 0u);
                unsigned status = st >> 30;
                if (status == 0u) { __nanosleep(40); continue; }
                running += (int)(st & 0x3FFFFFFFu);
                if (status == 2u) break;
                p--;
            }
            __threadfence();
            atomicExch(&state[b], (2u << 30) | (unsigned)(running + btot));
            s_base = running;
        }
    }

    // fused prescale: hh row i = half(dinv * x row i); overlaps lookback wait
    if (i < N_NODES) {
        const float4* __restrict__ xr =
            reinterpret_cast<const float4*>(x + (size_t)i * 32);
        uint2* __restrict__ hr = reinterpret_cast<uint2*>(g_hh) + (size_t)i * 8;
#pragma unroll
        for (int k = 0; k < 8; k++) {
            float4 v = xr[k];
            __half2 h0 = __floats2half2_rn(v.x * dv, v.y * dv);
            __half2 h1 = __floats2half2_rn(v.z * dv, v.w * dv);
            uint2 u;
            u.x = *reinterpret_cast<uint32_t*>(&h0);
            u.y = *reinterpret_cast<uint32_t*>(&h1);
            hr[k] = u;
        }
    }

    __syncthreads();
    int base = s_base;
    if (i < N_NODES) g_offs[i] = base + lex;
    if (i == N_NODES - 1) g_offs[N_NODES] = base + lex + c;
}

// scatter src into CSR slots — no atomics, dst+rank from packed word; 4 edges/thread
__global__ void fill_k(const void* __restrict__ ei) {
    int e0 = (blockIdx.x * blockDim.x + threadIdx.x) * 4;
    if (e0 >= N_EDGES) return;
    int s0, s1, s2, s3;
    if (!g_is64) {
        int4 v = *reinterpret_cast<const int4*>((const int*)ei + e0);
        s0 = clampn(v.x); s1 = clampn(v.y); s2 = clampn(v.z); s3 = clampn(v.w);
    } else {
        const long long* p = (const long long*)ei + e0;
        s0 = clampn(p[0]); s1 = clampn(p[1]); s2 = clampn(p[2]); s3 = clampn(p[3]);
    }
    int4 pr = *reinterpret_cast<const int4*>(g_rank + e0);
    g_srcl[g_offs[pr.x >> 14] + (pr.x & 0x3FFF)] = s0;
    g_srcl[g_offs[pr.y >> 14] + (pr.y & 0x3FFF)] = s1;
    g_srcl[g_offs[pr.z >> 14] + (pr.z & 0x3FFF)] = s2;
    g_srcl[g_offs[pr.w >> 14] + (pr.w & 0x3FFF)] = s3;
}

// ---------------- GEMM: out[N,FOUT] = in[N,FIN] @ W^T
template<int FIN, int FOUT, bool BR, bool OUTH>
__global__ void gemm_k(const float* __restrict__ x, const float* __restrict__ W,
                       const float* __restrict__ bias, void* __restrict__ hout) {
    constexpr int TPR = FOUT / 4;
    constexpr int RPB = 256 / TPR;
    __shared__ float Ws[FIN * FOUT];
    for (int i = threadIdx.x; i < FIN * FOUT; i += 256) {
        int f = i / FIN, k = i % FIN;
        Ws[k * FOUT + f] = W[i];
    }
    __syncthreads();

    int r  = threadIdx.x / TPR;
    int c0 = (threadIdx.x % TPR) * 4;
    int row = blockIdx.x * RPB + r;
    if (row >= N_NODES) return;

    const float4* __restrict__ xr = reinterpret_cast<const float4*>(x + (size_t)row * FIN);
    float a0 = 0.f, a1 = 0.f, a2 = 0.f, a3 = 0.f;
#pragma unroll
    for (int k4 = 0; k4 < FIN / 4; k4++) {
        float4 xv = xr[k4];
        const float4 w0 = *reinterpret_cast<const float4*>(&Ws[(4 * k4 + 0) * FOUT + c0]);
        const float4 w1 = *reinterpret_cast<const float4*>(&Ws[(4 * k4 + 1) * FOUT + c0]);
        const float4 w2 = *reinterpret_cast<const float4*>(&Ws[(4 * k4 + 2) * FOUT + c0]);
        const float4 w3 = *reinterpret_cast<const float4*>(&Ws[(4 * k4 + 3) * FOUT + c0]);
        a0 = fmaf(xv.x, w0.x, a0); a1 = fmaf(xv.x, w0.y, a1);
        a2 = fmaf(xv.x, w0.z, a2); a3 = fmaf(xv.x, w0.w, a3);
        a0 = fmaf(xv.y, w1.x, a0); a1 = fmaf(xv.y, w1.y, a1);
        a2 = fmaf(xv.y, w1.z, a2); a3 = fmaf(xv.y, w1.w, a3);
        a0 = fmaf(xv.z, w2.x, a0); a1 = fmaf(xv.z, w2.y, a1);
        a2 = fmaf(xv.z, w2.z, a2); a3 = fmaf(xv.z, w2.w, a3);
        a0 = fmaf(xv.w, w3.x, a0); a1 = fmaf(xv.w, w3.y, a1);
        a2 = fmaf(xv.w, w3.z, a2); a3 = fmaf(xv.w, w3.w, a3);
    }
    if (BR) {
        a0 = fmaxf(a0 + bias[c0 + 0], 0.f);
        a1 = fmaxf(a1 + bias[c0 + 1], 0.f);
        a2 = fmaxf(a2 + bias[c0 + 2], 0.f);
        a3 = fmaxf(a3 + bias[c0 + 3], 0.f);
    }
    if (OUTH) {
        float dv = g_dinv[row];
        __half2 h0 = __floats2half2_rn(a0 * dv, a1 * dv);
        __half2 h1 = __floats2half2_rn(a2 * dv, a3 * dv);
        uint2 u;
        u.x = *reinterpret_cast<uint32_t*>(&h0);
        u.y = *reinterpret_cast<uint32_t*>(&h1);
        reinterpret_cast<uint2*>(hout)[((size_t)row * FOUT + c0) >> 2] = u;
    } else {
        reinterpret_cast<float4*>(hout)[((size_t)row * FOUT + c0) >> 2] =
            make_float4(a0, a1, a2, a3);
    }
}

__device__ __forceinline__ void acc_half4(float& ax, float& ay, float& az, float& aw,
                                          uint2 u) {
    __half2 p0 = *reinterpret_cast<__half2*>(&u.x);
    __half2 p1 = *reinterpret_cast<__half2*>(&u.y);
    float2 f0 = __half22float2(p0);
    float2 f1 = __half22float2(p1);
    ax += f0.x; ay += f0.y; az += f1.x; aw += f1.y;
}

// ---------------- agg F=64 (fp16 in): 16 lanes x 4 halves per edge, 2 edges/iter
template<bool BR>
__global__ void agg64_k(const __half* __restrict__ h, const float* __restrict__ bias,
                        float* __restrict__ out) {
    int node = (blockIdx.x * blockDim.x + threadIdx.x) >> 5;
    int lane = threadIdx.x & 31;
    if (node >= N_NODES) return;
    int half = lane >> 4;
    int fl   = lane & 15;
    const uint2* __restrict__ h8 = reinterpret_cast<const uint2*>(h);

    int beg = g_offs[node];
    int end = g_offs[node + 1];

    float ax = 0.f, ay = 0.f, az = 0.f, aw = 0.f;
    int j = beg + half;
    for (; j + 2 < end; j += 4) {
        int s0 = g_srcl[j];
        int s1 = g_srcl[j + 2];
        uint2 u0 = h8[(size_t)s0 * 16 + fl];
        uint2 u1 = h8[(size_t)s1 * 16 + fl];
        acc_half4(ax, ay, az, aw, u0);
        acc_half4(ax, ay, az, aw, u1);
    }
    if (j < end) {
        int s = g_srcl[j];
        acc_half4(ax, ay, az, aw, h8[(size_t)s * 16 + fl]);
    }

    ax += __shfl_xor_sync(FULLM, ax, 16);
    ay += __shfl_xor_sync(FULLM, ay, 16);
    az += __shfl_xor_sync(FULLM, az, 16);
    aw += __shfl_xor_sync(FULLM, aw, 16);

    if (half == 0) {
        float dv = g_dinv[node];
        acc_half4(ax, ay, az, aw, h8[(size_t)node * 16 + fl]);   // self loop
        ax *= dv; ay *= dv; az *= dv; aw *= dv;
        if (BR) {
            const float4 bv = reinterpret_cast<const float4*>(bias)[fl];
            ax = fmaxf(ax + bv.x, 0.f); ay = fmaxf(ay + bv.y, 0.f);
            az = fmaxf(az + bv.z, 0.f); aw = fmaxf(aw + bv.w, 0.f);
        }
        reinterpret_cast<float4*>(out)[(size_t)node * 16 + fl] =
            make_float4(ax, ay, az, aw);
    }
}

// ---------------- agg F=32 (fp16 in): 8 lanes x 4 halves per edge, 4 edges/iter
template<bool BR>
__global__ void agg32_k(const __half* __restrict__ h, const float* __restrict__ bias,
                        float* __restrict__ out) {
    int node = (blockIdx.x * blockDim.x + threadIdx.x) >> 5;
    int lane = threadIdx.x & 31;
    if (node >= N_NODES) return;
    int q  = lane >> 3;
    int fl = lane & 7;
    const uint2* __restrict__ h8 = reinterpret_cast<const uint2*>(h);

    int beg = g_offs[node];
    int end = g_offs[node + 1];

    float ax = 0.f, ay = 0.f, az = 0.f, aw = 0.f;
    int j = beg + q;
    for (; j + 4 < end; j += 8) {
        int s0 = g_srcl[j];
        int s1 = g_srcl[j + 4];
        uint2 u0 = h8[(size_t)s0 * 8 + fl];
        uint2 u1 = h8[(size_t)s1 * 8 + fl];
        acc_half4(ax, ay, az, aw, u0);
        acc_half4(ax, ay, az, aw, u1);
    }
    if (j < end) {
        int s = g_srcl[j];
        acc_half4(ax, ay, az, aw, h8[(size_t)s * 8 + fl]);
    }

    ax += __shfl_xor_sync(FULLM, ax, 8);
    ay += __shfl_xor_sync(FULLM, ay, 8);
    az += __shfl_xor_sync(FULLM, az, 8);
    aw += __shfl_xor_sync(FULLM, aw, 8);
    ax += __shfl_xor_sync(FULLM, ax, 16);
    ay += __shfl_xor_sync(FULLM, ay, 16);
    az += __shfl_xor_sync(FULLM, az, 16);
    aw += __shfl_xor_sync(FULLM, aw, 16);

    if (q == 0) {
        float dv = g_dinv[node];
        acc_half4(ax, ay, az, aw, h8[(size_t)node * 8 + fl]);    // self loop
        ax *= dv; ay *= dv; az *= dv; aw *= dv;
        if (BR) {
            const float4 bv = reinterpret_cast<const float4*>(bias)[fl];
            ax = fmaxf(ax + bv.x, 0.f); ay = fmaxf(ay + bv.y, 0.f);
            az = fmaxf(az + bv.z, 0.f); aw = fmaxf(aw + bv.w, 0.f);
        }
        reinterpret_cast<float4*>(out)[(size_t)node * 8 + fl] =
            make_float4(ax, ay, az, aw);
    }
}

// ---------------- launch ----------------
extern "C" void kernel_launch(void* const* d_in, const int* in_sizes, int n_in,
                              void* d_out, int out_size) {
    const float* x  = (const float*)d_in[0];
    const void*  ei = d_in[1];
    const float* W1 = (const float*)d_in[2];
    const float* b1 = (const float*)d_in[3];
    const float* W2 = (const float*)d_in[4];
    const float* b2 = (const float*)d_in[5];
    const float* W3 = (const float*)d_in[6];
    const float* b3 = (const float*)d_in[7];
    float* out = (float*)d_out;

    void *phh, *py, *pa;
    cudaGetSymbolAddress(&phh, g_hh);
    cudaGetSymbolAddress(&py, g_y);
    cudaGetSymbolAddress(&pa, g_a);
    __half* hh = (__half*)phh;
    float*  y  = (float*)py;
    float*  a  = (float*)pa;

    const int TB = 256;
    const int WGRID  = (N_NODES * 32 + TB - 1) / TB;
    const int EGRID4 = (N_EDGES / 4 + TB - 1) / TB;
    const int IGRID  = (N_NODES + 512 + TB - 1) / TB;

    // CSR build (4 launches, no memset)
    init_detect_k<<<IGRID, TB>>>((const int*)ei);   // 1: zero cnt/state + dtype
    count_k<<<EGRID4, TB>>>(ei);                    // 2
    scan_k <<<NBLK, TB>>>(x);                       // 3: dinv + offs + x prescale
    fill_k <<<EGRID4, TB>>>(ei);                    // 4

    // Layer 1 (launch 5 = agg32, profiled)
    agg32_k<false><<<WGRID, TB>>>(hh, nullptr, a);
    gemm_k<32, 64, true, false><<<N_NODES / 16, TB>>>(a, W1, b1, y);
    // Layer 2
    gemm_k<64, 64, false, true><<<N_NODES / 16, TB>>>(y, W2, nullptr, hh);
    agg64_k<true><<<WGRID, TB>>>(hh, b2, y);
    // Layer 3
    gemm_k<64, 32, false, true><<<N_NODES / 32, TB>>>(y, W3, nullptr, hh);
    agg32_k<true><<<WGRID, TB>>>(hh, b3, out);

    (void)in_sizes; (void)n_in; (void)out_size;
}

// round 13
// speedup vs baseline: 1.7419x; 1.7339x over previous
#include <cuda_runtime.h>
#include <cuda_fp16.h>
#include <cstdint>

#define N_NODES 100000
#define N_PAD   (N_NODES + 128)
#define N_EDGES 1600000
#define NBLK 391          // ceil(N_NODES/256)
#define FULLM 0xFFFFFFFFu

// ---------------- device scratch (row-padded so GEMMs need no guards) -------
__device__ __half g_hh[(size_t)N_PAD * 64];     // fp16 gather operand
__device__ float  g_y[(size_t)N_PAD * 64];
__device__ float  g_a[(size_t)N_PAD * 32];
__device__ int    g_cnt[N_NODES + 512];         // counts + lookback state tail
__device__ float  g_dinv[N_PAD];
__device__ int    g_offs[N_NODES + 1];
__device__ int    g_rank[N_EDGES];              // packed (dst<<14)|rank
__device__ int    g_srcl[N_EDGES];              // CSR src indices
__device__ int    g_is64;

// ---------------- helpers ----------------
__device__ __forceinline__ int clampn(long long v) {
    if (v < 0) v = 0;
    if (v >= N_NODES) v = N_NODES - 1;
    return (int)v;
}

// zero counts + lookback state; block 0 warp 0 detects dtype
__global__ void init_detect_k(const int* __restrict__ ei32) {
    int i = blockIdx.x * blockDim.x + threadIdx.x;
    if (i < N_NODES + 512) g_cnt[i] = 0;
    if (blockIdx.x == 0 && threadIdx.x < 32) {
        int lane = threadIdx.x;
        int nz = (ei32[2 * lane + 1] != 0);
        unsigned m = __ballot_sync(FULLM, nz);
        if (lane == 0) g_is64 = (m == 0) ? 1 : 0;
    }
}

// count in-degree, pack (dst<<14)|rank per edge; 4 edges/thread
__global__ void count_k(const void* __restrict__ ei) {
    int e0 = (blockIdx.x * blockDim.x + threadIdx.x) * 4;
    if (e0 >= N_EDGES) return;
    int d0, d1, d2, d3;
    if (!g_is64) {
        int4 v = *reinterpret_cast<const int4*>((const int*)ei + N_EDGES + e0);
        d0 = clampn(v.x); d1 = clampn(v.y); d2 = clampn(v.z); d3 = clampn(v.w);
    } else {
        const long long* p = (const long long*)ei + N_EDGES + e0;
        d0 = clampn(p[0]); d1 = clampn(p[1]); d2 = clampn(p[2]); d3 = clampn(p[3]);
    }
    int4 r;
    r.x = (d0 << 14) | atomicAdd(&g_cnt[d0], 1);
    r.y = (d1 << 14) | atomicAdd(&g_cnt[d1], 1);
    r.z = (d2 << 14) | atomicAdd(&g_cnt[d2], 1);
    r.w = (d3 << 14) | atomicAdd(&g_cnt[d3], 1);
    *reinterpret_cast<int4*>(g_rank + e0) = r;
}

// single-pass exclusive scan (decoupled lookback) + fused dinv + fused x prescale
__global__ void scan_k(const float* __restrict__ x) {
    __shared__ int wsum[8];
    __shared__ int s_base;
    unsigned* state = (unsigned*)(g_cnt + N_NODES);
    int tid = threadIdx.x, b = blockIdx.x;
    int i = b * 256 + tid;
    int c = (i < N_NODES) ? g_cnt[i] : 0;
    float dv = rsqrtf((float)c + 1.0f);
    if (i < N_NODES) g_dinv[i] = dv;
    int lane = tid & 31, wid = tid >> 5;

    int inc = c;                                  // warp inclusive scan
#pragma unroll
    for (int d = 1; d < 32; d <<= 1) {
        int t = __shfl_up_sync(FULLM, inc, d);
        if (lane >= d) inc += t;
    }
    if (lane == 31) wsum[wid] = inc;
    __syncthreads();
    if (wid == 0) {
        int v = (lane < 8) ? wsum[lane] : 0;
#pragma unroll
        for (int d = 1; d < 8; d <<= 1) {
            int t = __shfl_up_sync(FULLM, v, d);
            if (lane >= d) v += t;
        }
        if (lane < 8) wsum[lane] = v;
    }
    __syncthreads();
    int warpbase = (wid == 0) ? 0 : wsum[wid - 1];
    int lex = warpbase + inc - c;                 // block-local exclusive
    int btot = wsum[7];

    if (tid == 0) {
        if (b == 0) {
            __threadfence();
            atomicExch(&state[0], (2u << 30) | (unsigned)btot);
            s_base = 0;
        } else {
            __threadfence();
            atomicExch(&state[b], (1u << 30) | (unsigned)btot);
            int running = 0;
            int p = b - 1;
            while (true) {
                unsigned st = atomicAdd(&state[p], 0u);
                unsigned status = st >> 30;
                if (status == 0u) { __nanosleep(40); continue; }
                running += (int)(st & 0x3FFFFFFFu);
                if (status == 2u) break;
                p--;
            }
            __threadfence();
            atomicExch(&state[b], (2u << 30) | (unsigned)(running + btot));
            s_base = running;
        }
    }

    // fused prescale: hh row i = half(dinv * x row i); overlaps lookback wait
    if (i < N_NODES) {
        const float4* __restrict__ xr =
            reinterpret_cast<const float4*>(x + (size_t)i * 32);
        uint2* __restrict__ hr = reinterpret_cast<uint2*>(g_hh) + (size_t)i * 8;
#pragma unroll
        for (int k = 0; k < 8; k++) {
            float4 v = xr[k];
            __half2 h0 = __floats2half2_rn(v.x * dv, v.y * dv);
            __half2 h1 = __floats2half2_rn(v.z * dv, v.w * dv);
            uint2 u;
            u.x = *reinterpret_cast<uint32_t*>(&h0);
            u.y = *reinterpret_cast<uint32_t*>(&h1);
            hr[k] = u;
        }
    }

    __syncthreads();
    int base = s_base;
    if (i < N_NODES) g_offs[i] = base + lex;
    if (i == N_NODES - 1) g_offs[N_NODES] = base + lex + c;
}

// scatter src into CSR slots — no atomics, dst+rank from packed word; 4 edges/thread
__global__ void fill_k(const void* __restrict__ ei) {
    int e0 = (blockIdx.x * blockDim.x + threadIdx.x) * 4;
    if (e0 >= N_EDGES) return;
    int s0, s1, s2, s3;
    if (!g_is64) {
        int4 v = *reinterpret_cast<const int4*>((const int*)ei + e0);
        s0 = clampn(v.x); s1 = clampn(v.y); s2 = clampn(v.z); s3 = clampn(v.w);
    } else {
        const long long* p = (const long long*)ei + e0;
        s0 = clampn(p[0]); s1 = clampn(p[1]); s2 = clampn(p[2]); s3 = clampn(p[3]);
    }
    int4 pr = *reinterpret_cast<const int4*>(g_rank + e0);
    g_srcl[g_offs[pr.x >> 14] + (pr.x & 0x3FFF)] = s0;
    g_srcl[g_offs[pr.y >> 14] + (pr.y & 0x3FFF)] = s1;
    g_srcl[g_offs[pr.z >> 14] + (pr.z & 0x3FFF)] = s2;
    g_srcl[g_offs[pr.w >> 14] + (pr.w & 0x3FFF)] = s3;
}

// ---------------- GEMM: out[N,FOUT] = in[N,FIN] @ W^T, 4-row register tile ----
// Each thread: 4 rows x 4 cols. W loaded from smem ONCE per k-step, reused 4x.
template<int FIN, int FOUT, bool BR, bool OUTH>
__global__ void gemm_k(const float* __restrict__ x, const float* __restrict__ W,
                       const float* __restrict__ bias, void* __restrict__ hout) {
    constexpr int TPR  = FOUT / 4;       // threads per row-group
    constexpr int RGPB = 256 / TPR;      // row-groups per block
    __shared__ float Ws[FIN * FOUT];     // Ws[k*FOUT + f] = W[f*FIN + k]
    for (int i = threadIdx.x; i < FIN * FOUT; i += 256) {
        int f = i / FIN, k = i % FIN;
        Ws[k * FOUT + f] = W[i];
    }
    __syncthreads();

    int rg  = threadIdx.x / TPR;
    int c0  = (threadIdx.x % TPR) * 4;
    int row0 = (blockIdx.x * RGPB + rg) * 4;     // rows row0..row0+3 (padded, no guard)

    const float4* __restrict__ xr0 = reinterpret_cast<const float4*>(x + (size_t)(row0 + 0) * FIN);
    const float4* __restrict__ xr1 = reinterpret_cast<const float4*>(x + (size_t)(row0 + 1) * FIN);
    const float4* __restrict__ xr2 = reinterpret_cast<const float4*>(x + (size_t)(row0 + 2) * FIN);
    const float4* __restrict__ xr3 = reinterpret_cast<const float4*>(x + (size_t)(row0 + 3) * FIN);

    float acc[4][4];
#pragma unroll
    for (int r = 0; r < 4; r++)
#pragma unroll
        for (int c = 0; c < 4; c++) acc[r][c] = 0.f;

#pragma unroll
    for (int k4 = 0; k4 < FIN / 4; k4++) {
        const float4 w0 = *reinterpret_cast<const float4*>(&Ws[(4 * k4 + 0) * FOUT + c0]);
        const float4 w1 = *reinterpret_cast<const float4*>(&Ws[(4 * k4 + 1) * FOUT + c0]);
        const float4 w2 = *reinterpret_cast<const float4*>(&Ws[(4 * k4 + 2) * FOUT + c0]);
        const float4 w3 = *reinterpret_cast<const float4*>(&Ws[(4 * k4 + 3) * FOUT + c0]);
        float4 xv[4];
        xv[0] = xr0[k4]; xv[1] = xr1[k4]; xv[2] = xr2[k4]; xv[3] = xr3[k4];
#pragma unroll
        for (int r = 0; r < 4; r++) {
            acc[r][0] = fmaf(xv[r].x, w0.x, acc[r][0]);
            acc[r][1] = fmaf(xv[r].x, w0.y, acc[r][1]);
            acc[r][2] = fmaf(xv[r].x, w0.z, acc[r][2]);
            acc[r][3] = fmaf(xv[r].x, w0.w, acc[r][3]);
            acc[r][0] = fmaf(xv[r].y, w1.x, acc[r][0]);
            acc[r][1] = fmaf(xv[r].y, w1.y, acc[r][1]);
            acc[r][2] = fmaf(xv[r].y, w1.z, acc[r][2]);
            acc[r][3] = fmaf(xv[r].y, w1.w, acc[r][3]);
            acc[r][0] = fmaf(xv[r].z, w2.x, acc[r][0]);
            acc[r][1] = fmaf(xv[r].z, w2.y, acc[r][1]);
            acc[r][2] = fmaf(xv[r].z, w2.z, acc[r][2]);
            acc[r][3] = fmaf(xv[r].z, w2.w, acc[r][3]);
            acc[r][0] = fmaf(xv[r].w, w3.x, acc[r][0]);
            acc[r][1] = fmaf(xv[r].w, w3.y, acc[r][1]);
            acc[r][2] = fmaf(xv[r].w, w3.z, acc[r][2]);
            acc[r][3] = fmaf(xv[r].w, w3.w, acc[r][3]);
        }
    }

#pragma unroll
    for (int r = 0; r < 4; r++) {
        int row = row0 + r;
        float a0 = acc[r][0], a1 = acc[r][1], a2 = acc[r][2], a3 = acc[r][3];
        if (BR) {
            a0 = fmaxf(a0 + bias[c0 + 0], 0.f);
            a1 = fmaxf(a1 + bias[c0 + 1], 0.f);
            a2 = fmaxf(a2 + bias[c0 + 2], 0.f);
            a3 = fmaxf(a3 + bias[c0 + 3], 0.f);
        }
        if (OUTH) {
            float dv = g_dinv[row];
            __half2 h0 = __floats2half2_rn(a0 * dv, a1 * dv);
            __half2 h1 = __floats2half2_rn(a2 * dv, a3 * dv);
            uint2 u;
            u.x = *reinterpret_cast<uint32_t*>(&h0);
            u.y = *reinterpret_cast<uint32_t*>(&h1);
            reinterpret_cast<uint2*>(hout)[((size_t)row * FOUT + c0) >> 2] = u;
        } else {
            reinterpret_cast<float4*>(hout)[((size_t)row * FOUT + c0) >> 2] =
                make_float4(a0, a1, a2, a3);
        }
    }
}

__device__ __forceinline__ void acc_half4(float& ax, float& ay, float& az, float& aw,
                                          uint2 u) {
    __half2 p0 = *reinterpret_cast<__half2*>(&u.x);
    __half2 p1 = *reinterpret_cast<__half2*>(&u.y);
    float2 f0 = __half22float2(p0);
    float2 f1 = __half22float2(p1);
    ax += f0.x; ay += f0.y; az += f1.x; aw += f1.y;
}

// ---------------- agg F=64 (fp16 in): 16 lanes x 4 halves per edge, 2 edges/iter
template<bool BR>
__global__ void agg64_k(const __half* __restrict__ h, const float* __restrict__ bias,
                        float* __restrict__ out) {
    int node = (blockIdx.x * blockDim.x + threadIdx.x) >> 5;
    int lane = threadIdx.x & 31;
    if (node >= N_NODES) return;
    int half = lane >> 4;
    int fl   = lane & 15;
    const uint2* __restrict__ h8 = reinterpret_cast<const uint2*>(h);

    int beg = g_offs[node];
    int end = g_offs[node + 1];

    float ax = 0.f, ay = 0.f, az = 0.f, aw = 0.f;
    int j = beg + half;
    for (; j + 2 < end; j += 4) {
        int s0 = g_srcl[j];
        int s1 = g_srcl[j + 2];
        uint2 u0 = h8[(size_t)s0 * 16 + fl];
        uint2 u1 = h8[(size_t)s1 * 16 + fl];
        acc_half4(ax, ay, az, aw, u0);
        acc_half4(ax, ay, az, aw, u1);
    }
    if (j < end) {
        int s = g_srcl[j];
        acc_half4(ax, ay, az, aw, h8[(size_t)s * 16 + fl]);
    }

    ax += __shfl_xor_sync(FULLM, ax, 16);
    ay += __shfl_xor_sync(FULLM, ay, 16);
    az += __shfl_xor_sync(FULLM, az, 16);
    aw += __shfl_xor_sync(FULLM, aw, 16);

    if (half == 0) {
        float dv = g_dinv[node];
        acc_half4(ax, ay, az, aw, h8[(size_t)node * 16 + fl]);   // self loop
        ax *= dv; ay *= dv; az *= dv; aw *= dv;
        if (BR) {
            const float4 bv = reinterpret_cast<const float4*>(bias)[fl];
            ax = fmaxf(ax + bv.x, 0.f); ay = fmaxf(ay + bv.y, 0.f);
            az = fmaxf(az + bv.z, 0.f); aw = fmaxf(aw + bv.w, 0.f);
        }
        reinterpret_cast<float4*>(out)[(size_t)node * 16 + fl] =
            make_float4(ax, ay, az, aw);
    }
}

// ---------------- agg F=32 (fp16 in): 8 lanes x 4 halves per edge, 4 edges/iter
template<bool BR>
__global__ void agg32_k(const __half* __restrict__ h, const float* __restrict__ bias,
                        float* __restrict__ out) {
    int node = (blockIdx.x * blockDim.x + threadIdx.x) >> 5;
    int lane = threadIdx.x & 31;
    if (node >= N_NODES) return;
    int q  = lane >> 3;
    int fl = lane & 7;
    const uint2* __restrict__ h8 = reinterpret_cast<const uint2*>(h);

    int beg = g_offs[node];
    int end = g_offs[node + 1];

    float ax = 0.f, ay = 0.f, az = 0.f, aw = 0.f;
    int j = beg + q;
    for (; j + 4 < end; j += 8) {
        int s0 = g_srcl[j];
        int s1 = g_srcl[j + 4];
        uint2 u0 = h8[(size_t)s0 * 8 + fl];
        uint2 u1 = h8[(size_t)s1 * 8 + fl];
        acc_half4(ax, ay, az, aw, u0);
        acc_half4(ax, ay, az, aw, u1);
    }
    if (j < end) {
        int s = g_srcl[j];
        acc_half4(ax, ay, az, aw, h8[(size_t)s * 8 + fl]);
    }

    ax += __shfl_xor_sync(FULLM, ax, 8);
    ay += __shfl_xor_sync(FULLM, ay, 8);
    az += __shfl_xor_sync(FULLM, az, 8);
    aw += __shfl_xor_sync(FULLM, aw, 8);
    ax += __shfl_xor_sync(FULLM, ax, 16);
    ay += __shfl_xor_sync(FULLM, ay, 16);
    az += __shfl_xor_sync(FULLM, az, 16);
    aw += __shfl_xor_sync(FULLM, aw, 16);

    if (q == 0) {
        float dv = g_dinv[node];
        acc_half4(ax, ay, az, aw, h8[(size_t)node * 8 + fl]);    // self loop
        ax *= dv; ay *= dv; az *= dv; aw *= dv;
        if (BR) {
            const float4 bv = reinterpret_cast<const float4*>(bias)[fl];
            ax = fmaxf(ax + bv.x, 0.f); ay = fmaxf(ay + bv.y, 0.f);
            az = fmaxf(az + bv.z, 0.f); aw = fmaxf(aw + bv.w, 0.f);
        }
        reinterpret_cast<float4*>(out)[(size_t)node * 8 + fl] =
            make_float4(ax, ay, az, aw);
    }
}

// ---------------- launch ----------------
extern "C" void kernel_launch(void* const* d_in, const int* in_sizes, int n_in,
                              void* d_out, int out_size) {
    const float* x  = (const float*)d_in[0];
    const void*  ei = d_in[1];
    const float* W1 = (const float*)d_in[2];
    const float* b1 = (const float*)d_in[3];
    const float* W2 = (const float*)d_in[4];
    const float* b2 = (const float*)d_in[5];
    const float* W3 = (const float*)d_in[6];
    const float* b3 = (const float*)d_in[7];
    float* out = (float*)d_out;

    void *phh, *py, *pa;
    cudaGetSymbolAddress(&phh, g_hh);
    cudaGetSymbolAddress(&py, g_y);
    cudaGetSymbolAddress(&pa, g_a);
    __half* hh = (__half*)phh;
    float*  y  = (float*)py;
    float*  a  = (float*)pa;

    const int TB = 256;
    const int WGRID  = (N_NODES * 32 + TB - 1) / TB;
    const int EGRID4 = (N_EDGES / 4 + TB - 1) / TB;
    const int IGRID  = (N_NODES + 512 + TB - 1) / TB;
    const int G64 = (N_NODES + 63) / 64;     // gemm grids: 64 rows/block (FOUT=64)
    const int G32 = (N_NODES + 127) / 128;   // 128 rows/block (FOUT=32)

    // CSR build
    init_detect_k<<<IGRID, TB>>>((const int*)ei);
    count_k<<<EGRID4, TB>>>(ei);
    scan_k <<<NBLK, TB>>>(x);                 // dinv + offs + x prescale
    fill_k <<<EGRID4, TB>>>(ei);

    // Layer 1
    agg32_k<false><<<WGRID, TB>>>(hh, nullptr, a);
    gemm_k<32, 64, true, false><<<G64, TB>>>(a, W1, b1, y);
    // Layer 2
    gemm_k<64, 64, false, true><<<G64, TB>>>(y, W2, nullptr, hh);
    agg64_k<true><<<WGRID, TB>>>(hh, b2, y);
    // Layer 3
    gemm_k<64, 32, false, true><<<G32, TB>>>(y, W3, nullptr, hh);
    agg32_k<true><<<WGRID, TB>>>(hh, b3, out);

    (void)in_sizes; (void)n_in; (void)out_size;
}

// round 15
// speedup vs baseline: 1.9174x; 1.1008x over previous
#include <cuda_runtime.h>
#include <cuda_fp16.h>
#include <cstdint>

#define N_NODES 100000
#define N_PAD   (N_NODES + 128)
#define N_EDGES 1600000
#define NBLK 391          // ceil(N_NODES/256)
#define FULLM 0xFFFFFFFFu

// ---------------- device scratch (row-padded so GEMMs need no guards) -------
__device__ __half g_hh[(size_t)N_PAD * 64];     // fp16 gather operand
__device__ float  g_y[(size_t)N_PAD * 64];
__device__ float  g_a[(size_t)N_PAD * 32];
__device__ int    g_cnt[N_NODES + 512];         // counts + lookback state tail
__device__ float  g_dinv[N_PAD];
__device__ int    g_offs[N_NODES + 1];
__device__ int    g_rank[N_EDGES];              // packed (dst<<14)|rank
__device__ int    g_srcl[N_EDGES];              // CSR src indices
__device__ int    g_is64;

// ---------------- helpers ----------------
__device__ __forceinline__ int clampn(long long v) {
    if (v < 0) v = 0;
    if (v >= N_NODES) v = N_NODES - 1;
    return (int)v;
}

// zero counts + lookback state; block 0 warp 0 detects dtype
__global__ void init_detect_k(const int* __restrict__ ei32) {
    int i = blockIdx.x * blockDim.x + threadIdx.x;
    if (i < N_NODES + 512) g_cnt[i] = 0;
    if (blockIdx.x == 0 && threadIdx.x < 32) {
        int lane = threadIdx.x;
        int nz = (ei32[2 * lane + 1] != 0);
        unsigned m = __ballot_sync(FULLM, nz);
        if (lane == 0) g_is64 = (m == 0) ? 1 : 0;
    }
}

// count in-degree, pack (dst<<14)|rank per edge; 4 edges/thread
__global__ void count_k(const void* __restrict__ ei) {
    int e0 = (blockIdx.x * blockDim.x + threadIdx.x) * 4;
    if (e0 >= N_EDGES) return;
    int d0, d1, d2, d3;
    if (!g_is64) {
        int4 v = *reinterpret_cast<const int4*>((const int*)ei + N_EDGES + e0);
        d0 = clampn(v.x); d1 = clampn(v.y); d2 = clampn(v.z); d3 = clampn(v.w);
    } else {
        const long long* p = (const long long*)ei + N_EDGES + e0;
        d0 = clampn(p[0]); d1 = clampn(p[1]); d2 = clampn(p[2]); d3 = clampn(p[3]);
    }
    int4 r;
    r.x = (d0 << 14) | atomicAdd(&g_cnt[d0], 1);
    r.y = (d1 << 14) | atomicAdd(&g_cnt[d1], 1);
    r.z = (d2 << 14) | atomicAdd(&g_cnt[d2], 1);
    r.w = (d3 << 14) | atomicAdd(&g_cnt[d3], 1);
    *reinterpret_cast<int4*>(g_rank + e0) = r;
}

// single-pass exclusive scan (decoupled lookback) + fused dinv + fused x prescale
__global__ void scan_k(const float* __restrict__ x) {
    __shared__ int wsum[8];
    __shared__ int s_base;
    unsigned* state = (unsigned*)(g_cnt + N_NODES);
    int tid = threadIdx.x, b = blockIdx.x;
    int i = b * 256 + tid;
    int c = (i < N_NODES) ? g_cnt[i] : 0;
    float dv = rsqrtf((float)c + 1.0f);
    if (i < N_NODES) g_dinv[i] = dv;
    int lane = tid & 31, wid = tid >> 5;

    int inc = c;                                  // warp inclusive scan
#pragma unroll
    for (int d = 1; d < 32; d <<= 1) {
        int t = __shfl_up_sync(FULLM, inc, d);
        if (lane >= d) inc += t;
    }
    if (lane == 31) wsum[wid] = inc;
    __syncthreads();
    if (wid == 0) {
        int v = (lane < 8) ? wsum[lane] : 0;
#pragma unroll
        for (int d = 1; d < 8; d <<= 1) {
            int t = __shfl_up_sync(FULLM, v, d);
            if (lane >= d) v += t;
        }
        if (lane < 8) wsum[lane] = v;
    }
    __syncthreads();
    int warpbase = (wid == 0) ? 0 : wsum[wid - 1];
    int lex = warpbase + inc - c;                 // block-local exclusive
    int btot = wsum[7];

    if (tid == 0) {
        if (b == 0) {
            __threadfence();
            atomicExch(&state[0], (2u << 30) | (unsigned)btot);
            s_base = 0;
        } else {
            __threadfence();
            atomicExch(&state[b], (1u << 30) | (unsigned)btot);
            int running = 0;
            int p = b - 1;
            while (true) {
                unsigned st = atomicAdd(&state[p], 0u);
                unsigned status = st >> 30;
                if (status == 0u) { __nanosleep(40); continue; }
                running += (int)(st & 0x3FFFFFFFu);
                if (status == 2u) break;
                p--;
            }
            __threadfence();
            atomicExch(&state[b], (2u << 30) | (unsigned)(running + btot));
            s_base = running;
        }
    }

    // fused prescale: hh row i = half(dinv * x row i); overlaps lookback wait
    if (i < N_NODES) {
        const float4* __restrict__ xr =
            reinterpret_cast<const float4*>(x + (size_t)i * 32);
        uint2* __restrict__ hr = reinterpret_cast<uint2*>(g_hh) + (size_t)i * 8;
#pragma unroll
        for (int k = 0; k < 8; k++) {
            float4 v = xr[k];
            __half2 h0 = __floats2half2_rn(v.x * dv, v.y * dv);
            __half2 h1 = __floats2half2_rn(v.z * dv, v.w * dv);
            uint2 u;
            u.x = *reinterpret_cast<uint32_t*>(&h0);
            u.y = *reinterpret_cast<uint32_t*>(&h1);
            hr[k] = u;
        }
    }

    __syncthreads();
    int base = s_base;
    if (i < N_NODES) g_offs[i] = base + lex;
    if (i == N_NODES - 1) g_offs[N_NODES] = base + lex + c;
}

// scatter src into CSR slots — no atomics, dst+rank from packed word; 4 edges/thread
__global__ void fill_k(const void* __restrict__ ei) {
    int e0 = (blockIdx.x * blockDim.x + threadIdx.x) * 4;
    if (e0 >= N_EDGES) return;
    int s0, s1, s2, s3;
    if (!g_is64) {
        int4 v = *reinterpret_cast<const int4*>((const int*)ei + e0);
        s0 = clampn(v.x); s1 = clampn(v.y); s2 = clampn(v.z); s3 = clampn(v.w);
    } else {
        const long long* p = (const long long*)ei + e0;
        s0 = clampn(p[0]); s1 = clampn(p[1]); s2 = clampn(p[2]); s3 = clampn(p[3]);
    }
    int4 pr = *reinterpret_cast<const int4*>(g_rank + e0);
    g_srcl[g_offs[pr.x >> 14] + (pr.x & 0x3FFF)] = s0;
    g_srcl[g_offs[pr.y >> 14] + (pr.y & 0x3FFF)] = s1;
    g_srcl[g_offs[pr.z >> 14] + (pr.z & 0x3FFF)] = s2;
    g_srcl[g_offs[pr.w >> 14] + (pr.w & 0x3FFF)] = s3;
}

// ---------------- GEMM: out[N,FOUT] = in[N,FIN] @ W^T, 8-row register tile ----
// Each thread: 8 rows x 4 cols. W loaded from smem ONCE per k-step, reused 8x.
template<int FIN, int FOUT, bool BR, bool OUTH>
__global__ void gemm_k(const float* __restrict__ x, const float* __restrict__ W,
                       const float* __restrict__ bias, void* __restrict__ hout) {
    constexpr int TPR  = FOUT / 4;       // threads per row-group
    constexpr int RGPB = 256 / TPR;      // row-groups per block
    __shared__ float Ws[FIN * FOUT];     // Ws[k*FOUT + f] = W[f*FIN + k]
    for (int i = threadIdx.x; i < FIN * FOUT; i += 256) {
        int f = i / FIN, k = i % FIN;
        Ws[k * FOUT + f] = W[i];
    }
    __syncthreads();

    int rg  = threadIdx.x / TPR;
    int c0  = (threadIdx.x % TPR) * 4;
    int row0 = (blockIdx.x * RGPB + rg) * 8;     // rows row0..row0+7 (padded)

    const float4* __restrict__ xb = reinterpret_cast<const float4*>(x);
    const size_t rstride = FIN / 4;              // float4s per row

    float acc[8][4];
#pragma unroll
    for (int r = 0; r < 8; r++)
#pragma unroll
        for (int c = 0; c < 4; c++) acc[r][c] = 0.f;

#pragma unroll
    for (int k4 = 0; k4 < FIN / 4; k4++) {
        const float4 w0 = *reinterpret_cast<const float4*>(&Ws[(4 * k4 + 0) * FOUT + c0]);
        const float4 w1 = *reinterpret_cast<const float4*>(&Ws[(4 * k4 + 1) * FOUT + c0]);
        const float4 w2 = *reinterpret_cast<const float4*>(&Ws[(4 * k4 + 2) * FOUT + c0]);
        const float4 w3 = *reinterpret_cast<const float4*>(&Ws[(4 * k4 + 3) * FOUT + c0]);
#pragma unroll
        for (int r = 0; r < 8; r++) {
            float4 xv = xb[(size_t)(row0 + r) * rstride + k4];
            acc[r][0] = fmaf(xv.x, w0.x, acc[r][0]);
            acc[r][1] = fmaf(xv.x, w0.y, acc[r][1]);
            acc[r][2] = fmaf(xv.x, w0.z, acc[r][2]);
            acc[r][3] = fmaf(xv.x, w0.w, acc[r][3]);
            acc[r][0] = fmaf(xv.y, w1.x, acc[r][0]);
            acc[r][1] = fmaf(xv.y, w1.y, acc[r][1]);
            acc[r][2] = fmaf(xv.y, w1.z, acc[r][2]);
            acc[r][3] = fmaf(xv.y, w1.w, acc[r][3]);
            acc[r][0] = fmaf(xv.z, w2.x, acc[r][0]);
            acc[r][1] = fmaf(xv.z, w2.y, acc[r][1]);
            acc[r][2] = fmaf(xv.z, w2.z, acc[r][2]);
            acc[r][3] = fmaf(xv.z, w2.w, acc[r][3]);
            acc[r][0] = fmaf(xv.w, w3.x, acc[r][0]);
            acc[r][1] = fmaf(xv.w, w3.y, acc[r][1]);
            acc[r][2] = fmaf(xv.w, w3.z, acc[r][2]);
            acc[r][3] = fmaf(xv.w, w3.w, acc[r][3]);
        }
    }

#pragma unroll
    for (int r = 0; r < 8; r++) {
        int row = row0 + r;
        float a0 = acc[r][0], a1 = acc[r][1], a2 = acc[r][2], a3 = acc[r][3];
        if (BR) {
            a0 = fmaxf(a0 + bias[c0 + 0], 0.f);
            a1 = fmaxf(a1 + bias[c0 + 1], 0.f);
            a2 = fmaxf(a2 + bias[c0 + 2], 0.f);
            a3 = fmaxf(a3 + bias[c0 + 3], 0.f);
        }
        if (OUTH) {
            float dv = g_dinv[row];
            __half2 h0 = __floats2half2_rn(a0 * dv, a1 * dv);
            __half2 h1 = __floats2half2_rn(a2 * dv, a3 * dv);
            uint2 u;
            u.x = *reinterpret_cast<uint32_t*>(&h0);
            u.y = *reinterpret_cast<uint32_t*>(&h1);
            reinterpret_cast<uint2*>(hout)[((size_t)row * FOUT + c0) >> 2] = u;
        } else {
            reinterpret_cast<float4*>(hout)[((size_t)row * FOUT + c0) >> 2] =
                make_float4(a0, a1, a2, a3);
        }
    }
}

__device__ __forceinline__ void acc_half4(float& ax, float& ay, float& az, float& aw,
                                          uint2 u) {
    __half2 p0 = *reinterpret_cast<__half2*>(&u.x);
    __half2 p1 = *reinterpret_cast<__half2*>(&u.y);
    float2 f0 = __half22float2(p0);
    float2 f1 = __half22float2(p1);
    ax += f0.x; ay += f0.y; az += f1.x; aw += f1.y;
}

// ---------------- agg F=64 (fp16 in): 16 lanes x 4 halves per edge, 2 edges/iter
template<bool BR>
__global__ void agg64_k(const __half* __restrict__ h, const float* __restrict__ bias,
                        float* __restrict__ out) {
    int node = (blockIdx.x * blockDim.x + threadIdx.x) >> 5;
    int lane = threadIdx.x & 31;
    if (node >= N_NODES) return;
    int half = lane >> 4;
    int fl   = lane & 15;
    const uint2* __restrict__ h8 = reinterpret_cast<const uint2*>(h);

    int beg = g_offs[node];
    int end = g_offs[node + 1];

    float ax = 0.f, ay = 0.f, az = 0.f, aw = 0.f;
    int j = beg + half;
    for (; j + 2 < end; j += 4) {
        int s0 = g_srcl[j];
        int s1 = g_srcl[j + 2];
        uint2 u0 = h8[(size_t)s0 * 16 + fl];
        uint2 u1 = h8[(size_t)s1 * 16 + fl];
        acc_half4(ax, ay, az, aw, u0);
        acc_half4(ax, ay, az, aw, u1);
    }
    if (j < end) {
        int s = g_srcl[j];
        acc_half4(ax, ay, az, aw, h8[(size_t)s * 16 + fl]);
    }

    ax += __shfl_xor_sync(FULLM, ax, 16);
    ay += __shfl_xor_sync(FULLM, ay, 16);
    az += __shfl_xor_sync(FULLM, az, 16);
    aw += __shfl_xor_sync(FULLM, aw, 16);

    if (half == 0) {
        float dv = g_dinv[node];
        acc_half4(ax, ay, az, aw, h8[(size_t)node * 16 + fl]);   // self loop
        ax *= dv; ay *= dv; az *= dv; aw *= dv;
        if (BR) {
            const float4 bv = reinterpret_cast<const float4*>(bias)[fl];
            ax = fmaxf(ax + bv.x, 0.f); ay = fmaxf(ay + bv.y, 0.f);
            az = fmaxf(az + bv.z, 0.f); aw = fmaxf(aw + bv.w, 0.f);
        }
        reinterpret_cast<float4*>(out)[(size_t)node * 16 + fl] =
            make_float4(ax, ay, az, aw);
    }
}

// ---------------- agg F=32 (fp16 in): 8 lanes x 4 halves per edge, 4 edges/iter
template<bool BR>
__global__ void agg32_k(const __half* __restrict__ h, const float* __restrict__ bias,
                        float* __restrict__ out) {
    int node = (blockIdx.x * blockDim.x + threadIdx.x) >> 5;
    int lane = threadIdx.x & 31;
    if (node >= N_NODES) return;
    int q  = lane >> 3;
    int fl = lane & 7;
    const uint2* __restrict__ h8 = reinterpret_cast<const uint2*>(h);

    int beg = g_offs[node];
    int end = g_offs[node + 1];

    float ax = 0.f, ay = 0.f, az = 0.f, aw = 0.f;
    int j = beg + q;
    for (; j + 4 < end; j += 8) {
        int s0 = g_srcl[j];
        int s1 = g_srcl[j + 4];
        uint2 u0 = h8[(size_t)s0 * 8 + fl];
        uint2 u1 = h8[(size_t)s1 * 8 + fl];
        acc_half4(ax, ay, az, aw, u0);
        acc_half4(ax, ay, az, aw, u1);
    }
    if (j < end) {
        int s = g_srcl[j];
        acc_half4(ax, ay, az, aw, h8[(size_t)s * 8 + fl]);
    }

    ax += __shfl_xor_sync(FULLM, ax, 8);
    ay += __shfl_xor_sync(FULLM, ay, 8);
    az += __shfl_xor_sync(FULLM, az, 8);
    aw += __shfl_xor_sync(FULLM, aw, 8);
    ax += __shfl_xor_sync(FULLM, ax, 16);
    ay += __shfl_xor_sync(FULLM, ay, 16);
    az += __shfl_xor_sync(FULLM, az, 16);
    aw += __shfl_xor_sync(FULLM, aw, 16);

    if (q == 0) {
        float dv = g_dinv[node];
        acc_half4(ax, ay, az, aw, h8[(size_t)node * 8 + fl]);    // self loop
        ax *= dv; ay *= dv; az *= dv; aw *= dv;
        if (BR) {
            const float4 bv = reinterpret_cast<const float4*>(bias)[fl];
            ax = fmaxf(ax + bv.x, 0.f); ay = fmaxf(ay + bv.y, 0.f);
            az = fmaxf(az + bv.z, 0.f); aw = fmaxf(aw + bv.w, 0.f);
        }
        reinterpret_cast<float4*>(out)[(size_t)node * 8 + fl] =
            make_float4(ax, ay, az, aw);
    }
}

// ---------------- launch ----------------
extern "C" void kernel_launch(void* const* d_in, const int* in_sizes, int n_in,
                              void* d_out, int out_size) {
    const float* x  = (const float*)d_in[0];
    const void*  ei = d_in[1];
    const float* W1 = (const float*)d_in[2];
    const float* b1 = (const float*)d_in[3];
    const float* W2 = (const float*)d_in[4];
    const float* b2 = (const float*)d_in[5];
    const float* W3 = (const float*)d_in[6];
    const float* b3 = (const float*)d_in[7];
    float* out = (float*)d_out;

    void *phh, *py, *pa;
    cudaGetSymbolAddress(&phh, g_hh);
    cudaGetSymbolAddress(&py, g_y);
    cudaGetSymbolAddress(&pa, g_a);
    __half* hh = (__half*)phh;
    float*  y  = (float*)py;
    float*  a  = (float*)pa;

    const int TB = 256;
    const int WGRID  = (N_NODES * 32 + TB - 1) / TB;
    const int EGRID4 = (N_EDGES / 4 + TB - 1) / TB;
    const int IGRID  = (N_NODES + 512 + TB - 1) / TB;
    const int G64 = (N_NODES + 127) / 128;   // FOUT=64: 128 rows/block
    const int G32 = (N_NODES + 255) / 256;   // FOUT=32: 256 rows/block

    // CSR build
    init_detect_k<<<IGRID, TB>>>((const int*)ei);
    count_k<<<EGRID4, TB>>>(ei);
    scan_k <<<NBLK, TB>>>(x);                 // dinv + offs + x prescale
    fill_k <<<EGRID4, TB>>>(ei);

    // Layer 1
    agg32_k<false><<<WGRID, TB>>>(hh, nullptr, a);
    gemm_k<32, 64, true, false><<<G64, TB>>>(a, W1, b1, y);
    // Layer 2
    gemm_k<64, 64, false, true><<<G64, TB>>>(y, W2, nullptr, hh);
    agg64_k<true><<<WGRID, TB>>>(hh, b2, y);
    // Layer 3
    gemm_k<64, 32, false, true><<<G32, TB>>>(y, W3, nullptr, hh);
    agg32_k<true><<<WGRID, TB>>>(hh, b3, out);

    (void)in_sizes; (void)n_in; (void)out_size;
}